// round 9
// baseline (speedup 1.0000x reference)
#include <cuda_runtime.h>
#include <cuda_bf16.h>
#include <mma.h>
#include <cmath>
#include <cstdint>

using namespace nvcuda;

// Problem dims
#define BB 4
#define NN 4096
#define CC 128

// Tiling
#define BM 64       // queries per CTA
#define BN 64       // key tile
#define NTHREADS 256

// qkv kernel smem ld (wmma path, generous pad)
#define LDA 136
// attention smem leading dims, chosen for conflict-free mma operand LDS:
//  A-pattern addr = (lane>>2)*LD + (lane&3)        -> LD % 32 == 4
//  B-pattern addr = (lane&3)*LD + (lane>>2) (V)    -> LD % 32 == 8
#define LDQ 132
#define LDK 132
#define LDV 136
#define LDP 68

// Scratch for Q,K,V projections (tf32-rounded fp32). __device__ globals: no allocs.
__device__ float g_q[BB * NN * CC];
__device__ float g_k[BB * NN * CC];
__device__ float g_v[BB * NN * CC];

// ---- helpers ---------------------------------------------------------------
__device__ __forceinline__ uint32_t smem_u32(const void* p) {
    return (uint32_t)__cvta_generic_to_shared(p);
}
__device__ __forceinline__ void cp_async16(uint32_t dst, const void* src) {
    asm volatile("cp.async.cg.shared.global [%0], [%1], 16;\n" :: "r"(dst), "l"(src));
}
__device__ __forceinline__ void cp_commit() {
    asm volatile("cp.async.commit_group;\n" ::: "memory");
}
template <int N>
__device__ __forceinline__ void cp_wait() {
    asm volatile("cp.async.wait_group %0;\n" :: "n"(N) : "memory");
}
__device__ __forceinline__ float f2tf32(float x) {
    uint32_t u;
    asm("cvt.rna.tf32.f32 %0, %1;" : "=r"(u) : "f"(x));
    return __uint_as_float(u);
}
// D += A*B, m16n8k8 tf32 (PTX-documented fragment layouts)
__device__ __forceinline__ void mma_tf32(float& d0, float& d1, float& d2, float& d3,
                                         uint32_t a0, uint32_t a1, uint32_t a2, uint32_t a3,
                                         uint32_t b0, uint32_t b1) {
    asm volatile("mma.sync.aligned.m16n8k8.row.col.f32.tf32.tf32.f32 "
                 "{%0,%1,%2,%3}, {%4,%5,%6,%7}, {%8,%9}, {%0,%1,%2,%3};\n"
                 : "+f"(d0), "+f"(d1), "+f"(d2), "+f"(d3)
                 : "r"(a0), "r"(a1), "r"(a2), "r"(a3), "r"(b0), "r"(b1));
}

// Issue a 64x128 fp32 tile load gmem->smem via cp.async.
// Row byte stride LD*4 must be 16B-aligned: LD % 4 == 0 (132, 136 OK).
template <int LD>
__device__ __forceinline__ void issue_tile_load(float* smem_dst, const float* gsrc, int tid) {
    #pragma unroll
    for (int i = tid; i < BM * 32; i += NTHREADS) {
        int r = i >> 5;
        int c = i & 31;
        cp_async16(smem_u32(smem_dst + r * LD + c * 4), gsrc + (size_t)r * CC + c * 4);
    }
}

// ---------------------------------------------------------------------------
// Kernel 1: fused QKV projection + bias + exact GELU (wmma tf32),
// output tf32-rounded so the attention MMAs need no operand conversion.
// ---------------------------------------------------------------------------
__global__ __launch_bounds__(NTHREADS)
void qkv_kernel(const float* __restrict__ x,
                const float* __restrict__ Wq, const float* __restrict__ bq,
                const float* __restrict__ Wk, const float* __restrict__ bk,
                const float* __restrict__ Wv, const float* __restrict__ bv)
{
    extern __shared__ float sm[];
    float* Xs   = sm;                 // 64 x LDA
    float* Ws   = Xs + BM * LDA;      // 128 x LDA
    float* Outs = Ws + CC * LDA;      // 64 x LDA

    const int tid  = threadIdx.x;
    const int warp = tid >> 5;
    const int row0 = blockIdx.x * BM;

    {
        const float4* g4 = reinterpret_cast<const float4*>(x + (size_t)row0 * CC);
        for (int i = tid; i < BM * (CC / 4); i += NTHREADS) {
            int r = i >> 5;
            int c = i & 31;
            reinterpret_cast<float4*>(Xs + r * LDA)[c] = g4[(size_t)r * 32 + c];
        }
    }

    const float* Wlist[3] = {Wq, Wk, Wv};
    const float* blist[3] = {bq, bk, bv};
    float* olist[3];
    olist[0] = g_q; olist[1] = g_k; olist[2] = g_v;

    for (int j = 0; j < 3; ++j) {
        __syncthreads();
        {
            const float4* g4 = reinterpret_cast<const float4*>(Wlist[j]);
            for (int i = tid; i < CC * (CC / 4); i += NTHREADS) {
                int r = i >> 5;
                int c = i & 31;
                reinterpret_cast<float4*>(Ws + r * LDA)[c] = g4[(size_t)r * 32 + c];
            }
        }
        __syncthreads();

        {
            const int tr  = warp >> 1;
            const int tc0 = (warp & 1) * 4;

            wmma::fragment<wmma::accumulator, 16, 16, 8, float> acc[4];
            #pragma unroll
            for (int f = 0; f < 4; ++f) wmma::fill_fragment(acc[f], 0.0f);

            for (int k0 = 0; k0 < CC; k0 += 8) {
                wmma::fragment<wmma::matrix_a, 16, 16, 8, wmma::precision::tf32, wmma::row_major> a;
                wmma::load_matrix_sync(a, Xs + tr * 16 * LDA + k0, LDA);
                #pragma unroll
                for (int i = 0; i < a.num_elements; ++i) a.x[i] = wmma::__float_to_tf32(a.x[i]);

                #pragma unroll
                for (int f = 0; f < 4; ++f) {
                    wmma::fragment<wmma::matrix_b, 16, 16, 8, wmma::precision::tf32, wmma::col_major> bf;
                    wmma::load_matrix_sync(bf, Ws + (tc0 + f) * 16 * LDA + k0, LDA);
                    #pragma unroll
                    for (int i = 0; i < bf.num_elements; ++i) bf.x[i] = wmma::__float_to_tf32(bf.x[i]);
                    wmma::mma_sync(acc[f], a, bf, acc[f]);
                }
            }
            #pragma unroll
            for (int f = 0; f < 4; ++f)
                wmma::store_matrix_sync(Outs + tr * 16 * LDA + (tc0 + f) * 16, acc[f], LDA,
                                        wmma::mem_row_major);
        }
        __syncthreads();

        {
            const float* bias = blist[j];
            float* og = olist[j];
            for (int i = tid; i < BM * CC; i += NTHREADS) {
                int r = i >> 7;
                int c = i & 127;
                float v = Outs[r * LDA + c] + bias[c];
                v = 0.5f * v * (1.0f + erff(v * 0.70710678118654752f));
                og[(size_t)(row0 + r) * CC + c] = f2tf32(v);   // pre-round for tf32 MMA
            }
        }
    }
}

// ---------------------------------------------------------------------------
// Kernel 2: flash attention, raw mma.m16n8k8.tf32, register-resident O AND Q.
// K AND V double-buffered. Simple pipeline, one group per iteration:
//   prologue: issue K0,V0,Q; commit; wait<0>; sync; load Q fragments -> regs
//   iter t:   [commit K_{t+1}+V_{t+1} into buf cur^1]
//             S (Q regs x Kbuf[cur]) | sync | softmax | sync
//             PV (reads Ss, Vbuf[cur])
//             [wait<0>] ; sync      // drain prefetch; guard Ss reuse
// Only drain-all waits -> no FIFO-depth accounting to get wrong.
// ---------------------------------------------------------------------------
__global__ __launch_bounds__(NTHREADS, 1)
void attn_kernel(float* __restrict__ out)
{
    extern __shared__ float sm[];
    float* Qs      = sm;                    // 64 x LDQ (staging only; read once)
    float* Ks0     = Qs  + BM * LDQ;        // 64 x LDK
    float* Ks1     = Ks0 + BN * LDK;        // 64 x LDK
    float* Vs0     = Ks1 + BN * LDK;        // 64 x LDV
    float* Vs1     = Vs0 + BN * LDV;        // 64 x LDV
    float* Ss      = Vs1 + BN * LDV;        // 64 x LDP
    float* m_s     = Ss  + BM * LDP;        // 64
    float* l_s     = m_s + BM;              // 64
    float* alpha_s = l_s + BM;              // 64

    const int tid  = threadIdx.x;
    const int warp = tid >> 5;
    const int lane = tid & 31;
    const int g    = lane >> 2;   // group 0..7
    const int t    = lane & 3;    // thread-in-group
    const int tr   = warp >> 1;   // 0..3: 16-row band
    const int tch  = warp & 1;    // column half

    const int b     = blockIdx.y;
    const int qrow0 = blockIdx.x * BM;
    const int T     = NN / BN;

    const float* qg  = g_q + ((size_t)b * NN + qrow0) * CC;
    const float* kgb = g_k + (size_t)b * NN * CC;
    const float* vgb = g_v + (size_t)b * NN * CC;

    float* Kbuf[2] = {Ks0, Ks1};
    float* Vbuf[2] = {Vs0, Vs1};

    // Prologue: one group with K0, V0, Q
    issue_tile_load<LDK>(Kbuf[0], kgb, tid);
    issue_tile_load<LDV>(Vbuf[0], vgb, tid);
    issue_tile_load<LDQ>(Qs, qg, tid);
    cp_commit();
    if (tid < BM) { m_s[tid] = -INFINITY; l_s[tid] = 0.0f; }
    cp_wait<0>();
    __syncthreads();

    // Hoist Q A-fragments into registers ONCE (16 k-blocks x 4 regs).
    // Exactly the values the S-phase previously re-loaded every iteration.
    uint32_t qreg[CC / 8][4];
    {
        const float* Qr0 = Qs + (16 * tr + g) * LDQ;
        const float* Qr1 = Qr0 + 8 * LDQ;
        #pragma unroll
        for (int kb = 0; kb < CC / 8; ++kb) {
            qreg[kb][0] = __float_as_uint(Qr0[8 * kb + t]);
            qreg[kb][1] = __float_as_uint(Qr1[8 * kb + t]);
            qreg[kb][2] = __float_as_uint(Qr0[8 * kb + t + 4]);
            qreg[kb][3] = __float_as_uint(Qr1[8 * kb + t + 4]);
        }
    }

    // Register O accumulator: 8 n-tiles x 4 regs
    float o[8][4] = {};

    for (int kt = 0; kt < T; ++kt) {
        const int  cur      = kt & 1;
        const bool has_next = (kt + 1 < T);

        // Prefetch next K and V into the alternate buffers (whole-iteration window)
        if (has_next) {
            issue_tile_load<LDK>(Kbuf[cur ^ 1], kgb + (size_t)(kt + 1) * BN * CC, tid);
            issue_tile_load<LDV>(Vbuf[cur ^ 1], vgb + (size_t)(kt + 1) * BN * CC, tid);
            cp_commit();
        }

        const float* Ks = Kbuf[cur];
        const float* Vs = Vbuf[cur];

        // ---- S = Q K^T : rows 16tr+{g,g+8}, 4 n-tiles of 8 at 32*tch ----
        {
            float sacc[4][4] = {};

            #pragma unroll
            for (int kb = 0; kb < CC / 8; ++kb) {
                const int k0 = 8 * kb;
                #pragma unroll
                for (int j = 0; j < 4; ++j) {
                    const float* Kr = Ks + (32 * tch + 8 * j + g) * LDK;
                    uint32_t b0 = __float_as_uint(Kr[k0 + t]);
                    uint32_t b1 = __float_as_uint(Kr[k0 + t + 4]);
                    mma_tf32(sacc[j][0], sacc[j][1], sacc[j][2], sacc[j][3],
                             qreg[kb][0], qreg[kb][1], qreg[kb][2], qreg[kb][3],
                             b0, b1);
                }
            }
            #pragma unroll
            for (int j = 0; j < 4; ++j) {
                int col = 32 * tch + 8 * j + 2 * t;
                *reinterpret_cast<float2*>(Ss + (16 * tr + g) * LDP + col) =
                    make_float2(sacc[j][0], sacc[j][1]);
                *reinterpret_cast<float2*>(Ss + (16 * tr + g + 8) * LDP + col) =
                    make_float2(sacc[j][2], sacc[j][3]);
            }
        }
        __syncthreads();

        // ---- online softmax: 4 threads/row, 16 cols each ----
        {
            const int row = tid >> 2;
            const int seg = tid & 3;
            float* srow = Ss + row * LDP + seg * 16;

            float sv[16];
            #pragma unroll
            for (int q4 = 0; q4 < 4; ++q4) {
                float4 v4 = reinterpret_cast<const float4*>(srow)[q4];
                sv[q4 * 4 + 0] = v4.x; sv[q4 * 4 + 1] = v4.y;
                sv[q4 * 4 + 2] = v4.z; sv[q4 * 4 + 3] = v4.w;
            }
            float lm = -INFINITY;
            #pragma unroll
            for (int c = 0; c < 16; ++c) lm = fmaxf(lm, sv[c]);
            lm = fmaxf(lm, __shfl_xor_sync(0xffffffffu, lm, 1));
            lm = fmaxf(lm, __shfl_xor_sync(0xffffffffu, lm, 2));

            const float mold = m_s[row];
            const float mnew = fmaxf(mold, lm);
            const float alpha = __expf(mold - mnew);   // 0 on first tile

            float ls = 0.0f;
            #pragma unroll
            for (int c = 0; c < 16; ++c) {
                float p = f2tf32(__expf(sv[c] - mnew)); // round: PV consumes exactly this
                sv[c] = p;
                ls += p;
            }
            #pragma unroll
            for (int q4 = 0; q4 < 4; ++q4)
                reinterpret_cast<float4*>(srow)[q4] =
                    make_float4(sv[q4 * 4 + 0], sv[q4 * 4 + 1], sv[q4 * 4 + 2], sv[q4 * 4 + 3]);

            ls += __shfl_xor_sync(0xffffffffu, ls, 1);
            ls += __shfl_xor_sync(0xffffffffu, ls, 2);

            if (seg == 0) {
                m_s[row]     = mnew;
                l_s[row]     = l_s[row] * alpha + ls;
                alpha_s[row] = alpha;
            }
        }
        __syncthreads();

        // ---- O = alpha*O + P V : register accumulator ----
        {
            const float alo = alpha_s[16 * tr + g];
            const float ahi = alpha_s[16 * tr + 8 + g];
            #pragma unroll
            for (int f = 0; f < 8; ++f) {
                o[f][0] *= alo; o[f][1] *= alo;
                o[f][2] *= ahi; o[f][3] *= ahi;
            }

            const float* Pr0 = Ss + (16 * tr + g) * LDP;
            const float* Pr1 = Pr0 + 8 * LDP;
            #pragma unroll
            for (int kk0 = 0; kk0 < BN; kk0 += 8) {
                uint32_t a0 = __float_as_uint(Pr0[kk0 + t]);
                uint32_t a1 = __float_as_uint(Pr1[kk0 + t]);
                uint32_t a2 = __float_as_uint(Pr0[kk0 + t + 4]);
                uint32_t a3 = __float_as_uint(Pr1[kk0 + t + 4]);
                #pragma unroll
                for (int f = 0; f < 8; ++f) {
                    int n0 = 64 * tch + 8 * f;
                    uint32_t b0 = __float_as_uint(Vs[(kk0 + t) * LDV + n0 + g]);
                    uint32_t b1 = __float_as_uint(Vs[(kk0 + t + 4) * LDV + n0 + g]);
                    mma_tf32(o[f][0], o[f][1], o[f][2], o[f][3],
                             a0, a1, a2, a3, b0, b1);
                }
            }
        }

        // Drain prefetch (K_{t+1}, V_{t+1} landed) and guard Ss reuse next iter.
        if (has_next) cp_wait<0>();
        __syncthreads();
    }

    // ---- epilogue: out = O / l, written from documented fragment layout ----
    {
        const float inv_lo = 1.0f / l_s[16 * tr + g];
        const float inv_hi = 1.0f / l_s[16 * tr + 8 + g];
        float* og = out + ((size_t)b * NN + qrow0) * CC;
        const int r0 = 16 * tr + g;
        #pragma unroll
        for (int f = 0; f < 8; ++f) {
            int col = 64 * tch + 8 * f + 2 * t;
            *reinterpret_cast<float2*>(og + (size_t)r0 * CC + col) =
                make_float2(o[f][0] * inv_lo, o[f][1] * inv_lo);
            *reinterpret_cast<float2*>(og + (size_t)(r0 + 8) * CC + col) =
                make_float2(o[f][2] * inv_hi, o[f][3] * inv_hi);
        }
    }
}

// ---------------------------------------------------------------------------
extern "C" void kernel_launch(void* const* d_in, const int* in_sizes, int n_in,
                              void* d_out, int out_size)
{
    const float* x  = (const float*)d_in[0];
    const float* Wq = (const float*)d_in[1];
    const float* bq = (const float*)d_in[2];
    const float* Wk = (const float*)d_in[3];
    const float* bk = (const float*)d_in[4];
    const float* Wv = (const float*)d_in[5];
    const float* bv = (const float*)d_in[6];
    float* out = (float*)d_out;

    const int smem_qkv  = (BM * LDA + CC * LDA + BM * LDA) * sizeof(float);   // ~136 KB
    const int smem_attn = (BM * LDQ + 2 * BN * LDK + 2 * BN * LDV + BM * LDP + 3 * BM)
                          * sizeof(float);                                    // ~185 KB

    cudaFuncSetAttribute(qkv_kernel,  cudaFuncAttributeMaxDynamicSharedMemorySize, smem_qkv);
    cudaFuncSetAttribute(attn_kernel, cudaFuncAttributeMaxDynamicSharedMemorySize, smem_attn);

    qkv_kernel<<<(BB * NN) / BM, NTHREADS, smem_qkv>>>(x, Wq, bq, Wk, bk, Wv, bv);

    dim3 grid(NN / BM, BB);
    attn_kernel<<<grid, NTHREADS, smem_attn>>>(out);
}

// round 11
// speedup vs baseline: 1.4361x; 1.4361x over previous
#include <cuda_runtime.h>
#include <cuda_bf16.h>
#include <mma.h>
#include <cmath>
#include <cstdint>

using namespace nvcuda;

// Problem dims
#define BB 4
#define NN 4096
#define CC 128

// Tiling
#define BM 64       // queries per CTA
#define BN 64       // key tile
#define NTHREADS 256

// qkv kernel smem ld (wmma path)
#define LDA 136
// attention smem leading dims (conflict-free for the mma operand patterns):
#define LDQ 132     // fp32, A-pattern (LD%32==4)
#define LDK 132     // fp32, B-pattern rows (LD%32==4)
#define LDP 68      // fp32 scores (LD%32==4)
#define LDVT 72     // bf16 V^T rows: 144B row (word stride 36 -> 4g+t distinct banks)
#define LDPB 72     // bf16 P rows: 144B row

// Scratch. Q,K fp32 (tf32-rounded); V bf16 TRANSPOSED [b][d][n].
__device__ float g_q[BB * NN * CC];
__device__ float g_k[BB * NN * CC];
__device__ __nv_bfloat16 g_vt[BB * CC * NN];

// ---- helpers ---------------------------------------------------------------
__device__ __forceinline__ uint32_t smem_u32(const void* p) {
    return (uint32_t)__cvta_generic_to_shared(p);
}
__device__ __forceinline__ void cp_async16(uint32_t dst, const void* src) {
    asm volatile("cp.async.cg.shared.global [%0], [%1], 16;\n" :: "r"(dst), "l"(src));
}
__device__ __forceinline__ void cp_commit() {
    asm volatile("cp.async.commit_group;\n" ::: "memory");
}
template <int N>
__device__ __forceinline__ void cp_wait() {
    asm volatile("cp.async.wait_group %0;\n" :: "n"(N) : "memory");
}
__device__ __forceinline__ float f2tf32(float x) {
    uint32_t u;
    asm("cvt.rna.tf32.f32 %0, %1;" : "=r"(u) : "f"(x));
    return __uint_as_float(u);
}
// D += A*B, m16n8k8 tf32
__device__ __forceinline__ void mma_tf32(float& d0, float& d1, float& d2, float& d3,
                                         uint32_t a0, uint32_t a1, uint32_t a2, uint32_t a3,
                                         uint32_t b0, uint32_t b1) {
    asm volatile("mma.sync.aligned.m16n8k8.row.col.f32.tf32.tf32.f32 "
                 "{%0,%1,%2,%3}, {%4,%5,%6,%7}, {%8,%9}, {%0,%1,%2,%3};\n"
                 : "+f"(d0), "+f"(d1), "+f"(d2), "+f"(d3)
                 : "r"(a0), "r"(a1), "r"(a2), "r"(a3), "r"(b0), "r"(b1));
}
// D += A*B, m16n8k16 bf16 (A: 4x b32 = 8 bf16, B: 2x b32 = 4 bf16)
__device__ __forceinline__ void mma_bf16(float& d0, float& d1, float& d2, float& d3,
                                         uint32_t a0, uint32_t a1, uint32_t a2, uint32_t a3,
                                         uint32_t b0, uint32_t b1) {
    asm volatile("mma.sync.aligned.m16n8k16.row.col.f32.bf16.bf16.f32 "
                 "{%0,%1,%2,%3}, {%4,%5,%6,%7}, {%8,%9}, {%0,%1,%2,%3};\n"
                 : "+f"(d0), "+f"(d1), "+f"(d2), "+f"(d3)
                 : "r"(a0), "r"(a1), "r"(a2), "r"(a3), "r"(b0), "r"(b1));
}

// 64x128 fp32 tile gmem->smem via cp.async (row stride LD*4 bytes, 16B aligned).
template <int LD>
__device__ __forceinline__ void issue_tile_load(float* smem_dst, const float* gsrc, int tid) {
    #pragma unroll
    for (int i = tid; i < BM * 32; i += NTHREADS) {
        int r = i >> 5;
        int c = i & 31;
        cp_async16(smem_u32(smem_dst + r * LD + c * 4), gsrc + (size_t)r * CC + c * 4);
    }
}
// V^T tile: 128 rows (dim d) x 64 bf16 (keys), from g_vt[b][d][kt*64 + ...]
__device__ __forceinline__ void issue_vt_load(__nv_bfloat16* dst, const __nv_bfloat16* gsrc,
                                              int tid) {
    #pragma unroll
    for (int i = tid; i < 128 * 8; i += NTHREADS) {
        int d = i >> 3;
        int c = i & 7;
        cp_async16(smem_u32(dst + d * LDVT + c * 8), gsrc + (size_t)d * NN + c * 8);
    }
}

// ---------------------------------------------------------------------------
// Kernel 1: fused QKV projection + bias + exact GELU (wmma tf32).
// Q,K written tf32-rounded fp32; V written bf16 TRANSPOSED (g_vt[b][d][n]).
// ---------------------------------------------------------------------------
__global__ __launch_bounds__(NTHREADS)
void qkv_kernel(const float* __restrict__ x,
                const float* __restrict__ Wq, const float* __restrict__ bq,
                const float* __restrict__ Wk, const float* __restrict__ bk,
                const float* __restrict__ Wv, const float* __restrict__ bv)
{
    extern __shared__ float sm[];
    float* Xs   = sm;                 // 64 x LDA
    float* Ws   = Xs + BM * LDA;      // 128 x LDA
    float* Outs = Ws + CC * LDA;      // 64 x LDA

    const int tid  = threadIdx.x;
    const int warp = tid >> 5;
    const int row0 = blockIdx.x * BM;

    {
        const float4* g4 = reinterpret_cast<const float4*>(x + (size_t)row0 * CC);
        for (int i = tid; i < BM * (CC / 4); i += NTHREADS) {
            int r = i >> 5;
            int c = i & 31;
            reinterpret_cast<float4*>(Xs + r * LDA)[c] = g4[(size_t)r * 32 + c];
        }
    }

    const float* Wlist[3] = {Wq, Wk, Wv};
    const float* blist[3] = {bq, bk, bv};

    for (int j = 0; j < 3; ++j) {
        __syncthreads();
        {
            const float4* g4 = reinterpret_cast<const float4*>(Wlist[j]);
            for (int i = tid; i < CC * (CC / 4); i += NTHREADS) {
                int r = i >> 5;
                int c = i & 31;
                reinterpret_cast<float4*>(Ws + r * LDA)[c] = g4[(size_t)r * 32 + c];
            }
        }
        __syncthreads();

        {
            const int tr  = warp >> 1;
            const int tc0 = (warp & 1) * 4;

            wmma::fragment<wmma::accumulator, 16, 16, 8, float> acc[4];
            #pragma unroll
            for (int f = 0; f < 4; ++f) wmma::fill_fragment(acc[f], 0.0f);

            for (int k0 = 0; k0 < CC; k0 += 8) {
                wmma::fragment<wmma::matrix_a, 16, 16, 8, wmma::precision::tf32, wmma::row_major> a;
                wmma::load_matrix_sync(a, Xs + tr * 16 * LDA + k0, LDA);
                #pragma unroll
                for (int i = 0; i < a.num_elements; ++i) a.x[i] = wmma::__float_to_tf32(a.x[i]);

                #pragma unroll
                for (int f = 0; f < 4; ++f) {
                    wmma::fragment<wmma::matrix_b, 16, 16, 8, wmma::precision::tf32, wmma::col_major> bf;
                    wmma::load_matrix_sync(bf, Ws + (tc0 + f) * 16 * LDA + k0, LDA);
                    #pragma unroll
                    for (int i = 0; i < bf.num_elements; ++i) bf.x[i] = wmma::__float_to_tf32(bf.x[i]);
                    wmma::mma_sync(acc[f], a, bf, acc[f]);
                }
            }
            #pragma unroll
            for (int f = 0; f < 4; ++f)
                wmma::store_matrix_sync(Outs + tr * 16 * LDA + (tc0 + f) * 16, acc[f], LDA,
                                        wmma::mem_row_major);
        }
        __syncthreads();

        {
            const float* bias = blist[j];
            const int bb = row0 / NN;      // block fully within one batch (4096 % 64 == 0)
            const int n0 = row0 % NN;
            for (int i = tid; i < BM * CC; i += NTHREADS) {
                int r = i >> 7;
                int c = i & 127;
                float v = Outs[r * LDA + c] + bias[c];
                v = 0.5f * v * (1.0f + erff(v * 0.70710678118654752f));
                if (j == 0) {
                    g_q[(size_t)(row0 + r) * CC + c] = f2tf32(v);
                } else if (j == 1) {
                    g_k[(size_t)(row0 + r) * CC + c] = f2tf32(v);
                } else {
                    // V: bf16, transposed [b][d][n]
                    g_vt[((size_t)bb * CC + c) * NN + n0 + r] = __float2bfloat16(v);
                }
            }
        }
    }
}

// ---------------------------------------------------------------------------
// Kernel 2: flash attention. S = QK^T in tf32 (fp32 smem), PV in bf16
// (P and V^T bf16 in smem, m16n8k16). O register-resident. 2 CTAs/SM.
//
// Pipeline (single-buffered K and V^T, FIFO-traced):
//   prologue: issue K0+Q -> commit(G0); issue V0 -> commit(G1)
//   iter t:
//     top:  cp_wait<1>  (retires oldest: K_t[+Q at t=0]); sync
//     S phase (Qs x Ks -> Ss fp32); sync
//     if t+1<T: issue K_{t+1} -> Ks; commit     (no readers of Ks until next S)
//     softmax: Ss -> P bf16 (l sums bf16-rounded p)
//     cp_wait<has_next ? 1 : 0>  (retires V_t); sync
//     PV (Ps x Vt, bf16 mma, O in regs); sync
//     if t+1<T: issue V_{t+1} -> Vt; commit
// ---------------------------------------------------------------------------
__global__ __launch_bounds__(NTHREADS, 2)
void attn_kernel(float* __restrict__ out)
{
    extern __shared__ char smraw[];
    float*          Qs  = (float*)(smraw);                    // 64x132 f32  (33792 B)
    float*          Ks  = (float*)(smraw + 33792);            // 64x132 f32  (33792 B)
    float*          Ss  = (float*)(smraw + 67584);            // 64x68  f32  (17408 B)
    __nv_bfloat16*  Vt  = (__nv_bfloat16*)(smraw + 84992);    // 128x72 bf16 (18432 B)
    __nv_bfloat16*  Ps  = (__nv_bfloat16*)(smraw + 103424);   // 64x72  bf16 ( 9216 B)
    float*          m_s = (float*)(smraw + 112640);           // 64
    float*          l_s = m_s + BM;                           // 64
    float*          alpha_s = l_s + BM;                       // 64
    // total 113408 B (~110.8 KB) -> 2 CTAs/SM

    const int tid  = threadIdx.x;
    const int warp = tid >> 5;
    const int lane = tid & 31;
    const int g    = lane >> 2;   // group 0..7
    const int t    = lane & 3;    // thread-in-group
    const int tr   = warp >> 1;   // 16-row band
    const int tch  = warp & 1;    // column half

    const int b     = blockIdx.y;
    const int qrow0 = blockIdx.x * BM;
    const int T     = NN / BN;

    const float*         qg   = g_q  + ((size_t)b * NN + qrow0) * CC;
    const float*         kgb  = g_k  + (size_t)b * NN * CC;
    const __nv_bfloat16* vtgb = g_vt + (size_t)b * CC * NN;

    // Prologue: G0 = {K0, Q}, G1 = {V0}
    issue_tile_load<LDK>(Ks, kgb, tid);
    issue_tile_load<LDQ>(Qs, qg, tid);
    cp_commit();
    issue_vt_load(Vt, vtgb, tid);
    cp_commit();
    if (tid < BM) { m_s[tid] = -INFINITY; l_s[tid] = 0.0f; }

    // Register O accumulator: 8 n-tiles x 4 regs
    float o[8][4] = {};

    for (int kt = 0; kt < T; ++kt) {
        const bool has_next = (kt + 1 < T);

        cp_wait<1>();        // K_kt (and Q at kt=0) landed; newest group may fly
        __syncthreads();

        // ---- S = Q K^T (tf32): rows 16tr+{g,g+8}, 4 n-tiles of 8 at 32*tch ----
        {
            float sacc[4][4] = {};
            const float* Qr0 = Qs + (16 * tr + g) * LDQ;
            const float* Qr1 = Qr0 + 8 * LDQ;

            #pragma unroll
            for (int kb = 0; kb < CC / 8; ++kb) {
                const int k0 = 8 * kb;
                uint32_t a0 = __float_as_uint(Qr0[k0 + t]);
                uint32_t a1 = __float_as_uint(Qr1[k0 + t]);
                uint32_t a2 = __float_as_uint(Qr0[k0 + t + 4]);
                uint32_t a3 = __float_as_uint(Qr1[k0 + t + 4]);
                #pragma unroll
                for (int j = 0; j < 4; ++j) {
                    const float* Kr = Ks + (32 * tch + 8 * j + g) * LDK;
                    uint32_t b0 = __float_as_uint(Kr[k0 + t]);
                    uint32_t b1 = __float_as_uint(Kr[k0 + t + 4]);
                    mma_tf32(sacc[j][0], sacc[j][1], sacc[j][2], sacc[j][3],
                             a0, a1, a2, a3, b0, b1);
                }
            }
            #pragma unroll
            for (int j = 0; j < 4; ++j) {
                int col = 32 * tch + 8 * j + 2 * t;
                *reinterpret_cast<float2*>(Ss + (16 * tr + g) * LDP + col) =
                    make_float2(sacc[j][0], sacc[j][1]);
                *reinterpret_cast<float2*>(Ss + (16 * tr + g + 8) * LDP + col) =
                    make_float2(sacc[j][2], sacc[j][3]);
            }
        }
        __syncthreads();

        // Prefetch K_{t+1} (Ks has no readers until next iteration's S)
        if (has_next) {
            issue_tile_load<LDK>(Ks, kgb + (size_t)(kt + 1) * BN * CC, tid);
            cp_commit();
        }

        // ---- online softmax: 4 threads/row, 16 cols each; P -> bf16 ----
        {
            const int row = tid >> 2;
            const int seg = tid & 3;
            const float* srow = Ss + row * LDP + seg * 16;

            float sv[16];
            #pragma unroll
            for (int q4 = 0; q4 < 4; ++q4) {
                float4 v4 = reinterpret_cast<const float4*>(srow)[q4];
                sv[q4 * 4 + 0] = v4.x; sv[q4 * 4 + 1] = v4.y;
                sv[q4 * 4 + 2] = v4.z; sv[q4 * 4 + 3] = v4.w;
            }
            float lm = -INFINITY;
            #pragma unroll
            for (int c = 0; c < 16; ++c) lm = fmaxf(lm, sv[c]);
            lm = fmaxf(lm, __shfl_xor_sync(0xffffffffu, lm, 1));
            lm = fmaxf(lm, __shfl_xor_sync(0xffffffffu, lm, 2));

            const float mold = m_s[row];
            const float mnew = fmaxf(mold, lm);
            const float alpha = __expf(mold - mnew);   // 0 on first tile

            float ls = 0.0f;
            uint32_t packed[8];
            #pragma unroll
            for (int c2 = 0; c2 < 8; ++c2) {
                float p0 = __expf(sv[2 * c2 + 0] - mnew);
                float p1 = __expf(sv[2 * c2 + 1] - mnew);
                __nv_bfloat16 pb0 = __float2bfloat16(p0);
                __nv_bfloat16 pb1 = __float2bfloat16(p1);
                ls += __bfloat162float(pb0) + __bfloat162float(pb1);  // l matches PV inputs
                packed[c2] = (uint32_t)__bfloat16_as_ushort(pb0)
                           | ((uint32_t)__bfloat16_as_ushort(pb1) << 16);
            }
            uint32_t* pdst = reinterpret_cast<uint32_t*>(Ps + row * LDPB + seg * 16);
            #pragma unroll
            for (int c2 = 0; c2 < 8; ++c2) pdst[c2] = packed[c2];

            ls += __shfl_xor_sync(0xffffffffu, ls, 1);
            ls += __shfl_xor_sync(0xffffffffu, ls, 2);

            if (seg == 0) {
                m_s[row]     = mnew;
                l_s[row]     = l_s[row] * alpha + ls;
                alpha_s[row] = alpha;
            }
        }
        if (has_next) cp_wait<1>(); else cp_wait<0>();   // V_kt landed
        __syncthreads();

        // ---- O = alpha*O + P V (bf16 m16n8k16): O rows 16tr+{g,g+8}, cols 64tch+.. ----
        {
            const float alo = alpha_s[16 * tr + g];
            const float ahi = alpha_s[16 * tr + 8 + g];
            #pragma unroll
            for (int f = 0; f < 8; ++f) {
                o[f][0] *= alo; o[f][1] *= alo;
                o[f][2] *= ahi; o[f][3] *= ahi;
            }

            const __nv_bfloat16* Pr0 = Ps + (16 * tr + g) * LDPB;
            const __nv_bfloat16* Pr1 = Pr0 + 8 * LDPB;
            #pragma unroll
            for (int kk = 0; kk < BN; kk += 16) {
                // A fragment (m16n8k16 bf16): pairs at k = kk+2t(+1), kk+2t+8(+1)
                uint32_t a0 = *reinterpret_cast<const uint32_t*>(Pr0 + kk + 2 * t);
                uint32_t a1 = *reinterpret_cast<const uint32_t*>(Pr1 + kk + 2 * t);
                uint32_t a2 = *reinterpret_cast<const uint32_t*>(Pr0 + kk + 2 * t + 8);
                uint32_t a3 = *reinterpret_cast<const uint32_t*>(Pr1 + kk + 2 * t + 8);
                #pragma unroll
                for (int f = 0; f < 8; ++f) {
                    int n = 64 * tch + 8 * f + g;
                    const __nv_bfloat16* vr = Vt + n * LDVT;
                    uint32_t b0 = *reinterpret_cast<const uint32_t*>(vr + kk + 2 * t);
                    uint32_t b1 = *reinterpret_cast<const uint32_t*>(vr + kk + 2 * t + 8);
                    mma_bf16(o[f][0], o[f][1], o[f][2], o[f][3],
                             a0, a1, a2, a3, b0, b1);
                }
            }
        }
        __syncthreads();   // all warps done reading Ps / Vt

        // Prefetch V_{t+1} (Vt has no readers until next PV, which waits)
        if (has_next) {
            issue_vt_load(Vt, vtgb + (size_t)(kt + 1) * BN, tid);
            cp_commit();
        }
    }

    // ---- epilogue: out = O / l ----
    {
        const float inv_lo = 1.0f / l_s[16 * tr + g];
        const float inv_hi = 1.0f / l_s[16 * tr + 8 + g];
        float* og = out + ((size_t)b * NN + qrow0) * CC;
        const int r0 = 16 * tr + g;
        #pragma unroll
        for (int f = 0; f < 8; ++f) {
            int col = 64 * tch + 8 * f + 2 * t;
            *reinterpret_cast<float2*>(og + (size_t)r0 * CC + col) =
                make_float2(o[f][0] * inv_lo, o[f][1] * inv_lo);
            *reinterpret_cast<float2*>(og + (size_t)(r0 + 8) * CC + col) =
                make_float2(o[f][2] * inv_hi, o[f][3] * inv_hi);
        }
    }
}

// ---------------------------------------------------------------------------
extern "C" void kernel_launch(void* const* d_in, const int* in_sizes, int n_in,
                              void* d_out, int out_size)
{
    const float* x  = (const float*)d_in[0];
    const float* Wq = (const float*)d_in[1];
    const float* bq = (const float*)d_in[2];
    const float* Wk = (const float*)d_in[3];
    const float* bk = (const float*)d_in[4];
    const float* Wv = (const float*)d_in[5];
    const float* bv = (const float*)d_in[6];
    float* out = (float*)d_out;

    const int smem_qkv  = (BM * LDA + CC * LDA + BM * LDA) * sizeof(float);   // ~136 KB
    const int smem_attn = 113408;                                             // ~110.8 KB -> 2 CTAs/SM

    cudaFuncSetAttribute(qkv_kernel,  cudaFuncAttributeMaxDynamicSharedMemorySize, smem_qkv);
    cudaFuncSetAttribute(attn_kernel, cudaFuncAttributeMaxDynamicSharedMemorySize, smem_attn);

    qkv_kernel<<<(BB * NN) / BM, NTHREADS, smem_qkv>>>(x, Wq, bq, Wk, bk, Wv, bv);

    // 256 CTAs, 2 per SM -> single wave on 148 SMs
    dim3 grid(NN / BM, BB);
    attn_kernel<<<grid, NTHREADS, smem_attn>>>(out);
}

// round 12
// speedup vs baseline: 1.5264x; 1.0629x over previous
#include <cuda_runtime.h>
#include <cuda_bf16.h>
#include <mma.h>
#include <cmath>
#include <cstdint>

using namespace nvcuda;

// Problem dims
#define BB 4
#define NN 4096
#define CC 128

// Tiling
#define BM 64
#define BN 64
#define NTHREADS 256

// qkv kernel smem ld
#define LDA 136
// attention smem strides (in words/b32):
//  Q/K rows: 4 groups of 36 words (32 data + 4 pad), row stride 144 words
//  V^T/P rows: 4 groups of 12 words (8 data + 4 pad), row stride 48 words
#define LDQW 144
#define LDVW 48
#define LDPW 48

// Scratch: Q,K fp32 tf32-rounded, PERMUTED columns pi(k)=32*(k&3)+(k>>2).
// V bf16 transposed [b][d][n], permuted within each 64-key tile.
__device__ float g_q[BB * NN * CC];
__device__ float g_k[BB * NN * CC];
__device__ __nv_bfloat16 g_vt[BB * CC * NN];

// ---- helpers ---------------------------------------------------------------
__device__ __forceinline__ uint32_t smem_u32(const void* p) {
    return (uint32_t)__cvta_generic_to_shared(p);
}
__device__ __forceinline__ void cp_async16(uint32_t dst, const void* src) {
    asm volatile("cp.async.cg.shared.global [%0], [%1], 16;\n" :: "r"(dst), "l"(src));
}
__device__ __forceinline__ void cp_commit() {
    asm volatile("cp.async.commit_group;\n" ::: "memory");
}
template <int N>
__device__ __forceinline__ void cp_wait() {
    asm volatile("cp.async.wait_group %0;\n" :: "n"(N) : "memory");
}
__device__ __forceinline__ float f2tf32(float x) {
    uint32_t u;
    asm("cvt.rna.tf32.f32 %0, %1;" : "=r"(u) : "f"(x));
    return __uint_as_float(u);
}
__device__ __forceinline__ void mma_tf32(float& d0, float& d1, float& d2, float& d3,
                                         uint32_t a0, uint32_t a1, uint32_t a2, uint32_t a3,
                                         uint32_t b0, uint32_t b1) {
    asm volatile("mma.sync.aligned.m16n8k8.row.col.f32.tf32.tf32.f32 "
                 "{%0,%1,%2,%3}, {%4,%5,%6,%7}, {%8,%9}, {%0,%1,%2,%3};\n"
                 : "+f"(d0), "+f"(d1), "+f"(d2), "+f"(d3)
                 : "r"(a0), "r"(a1), "r"(a2), "r"(a3), "r"(b0), "r"(b1));
}
__device__ __forceinline__ void mma_bf16(float& d0, float& d1, float& d2, float& d3,
                                         uint32_t a0, uint32_t a1, uint32_t a2, uint32_t a3,
                                         uint32_t b0, uint32_t b1) {
    asm volatile("mma.sync.aligned.m16n8k16.row.col.f32.bf16.bf16.f32 "
                 "{%0,%1,%2,%3}, {%4,%5,%6,%7}, {%8,%9}, {%0,%1,%2,%3};\n"
                 : "+f"(d0), "+f"(d1), "+f"(d2), "+f"(d3)
                 : "r"(a0), "r"(a1), "r"(a2), "r"(a3), "r"(b0), "r"(b1));
}

// Q/K tile load: 64 rows x 32 chunks(16B). gmem rows are permuted-dense (128 fl);
// smem rows are 144 words: chunk c -> group c>>3, within 4*(c&7).
__device__ __forceinline__ void issue_qk_load(float* dst, const float* gsrc, int tid) {
    #pragma unroll
    for (int i = tid; i < BM * 32; i += NTHREADS) {
        int r = i >> 5;
        int c = i & 31;
        int smw = 36 * (c >> 3) + 4 * (c & 7);
        cp_async16(smem_u32(dst + r * LDQW + smw), gsrc + (size_t)r * CC + 4 * c);
    }
}
// V^T tile: 128 rows x 8 chunks(16B, 8 bf16). gmem row-tiles permuted-dense (64 bf16);
// smem rows 48 b32 words: chunk c -> 12*(c>>1) + 4*(c&1).
__device__ __forceinline__ void issue_vt_load(uint32_t* dst, const __nv_bfloat16* gsrc, int tid) {
    #pragma unroll
    for (int i = tid; i < 128 * 8; i += NTHREADS) {
        int d = i >> 3;
        int c = i & 7;
        int smw = 12 * (c >> 1) + 4 * (c & 1);
        cp_async16(smem_u32(dst + d * LDVW + smw), gsrc + (size_t)d * NN + 8 * c);
    }
}

// ---------------------------------------------------------------------------
// Kernel 1: fused QKV projection + bias + exact GELU.
// Q/K stored tf32-rounded with permuted columns; V stored bf16 transposed,
// permuted within 64-key tiles.
// ---------------------------------------------------------------------------
__global__ __launch_bounds__(NTHREADS)
void qkv_kernel(const float* __restrict__ x,
                const float* __restrict__ Wq, const float* __restrict__ bq,
                const float* __restrict__ Wk, const float* __restrict__ bk,
                const float* __restrict__ Wv, const float* __restrict__ bv)
{
    extern __shared__ float sm[];
    float* Xs   = sm;
    float* Ws   = Xs + BM * LDA;
    float* Outs = Ws + CC * LDA;

    const int tid  = threadIdx.x;
    const int warp = tid >> 5;
    const int row0 = blockIdx.x * BM;

    {
        const float4* g4 = reinterpret_cast<const float4*>(x + (size_t)row0 * CC);
        for (int i = tid; i < BM * (CC / 4); i += NTHREADS) {
            int r = i >> 5;
            int c = i & 31;
            reinterpret_cast<float4*>(Xs + r * LDA)[c] = g4[(size_t)r * 32 + c];
        }
    }

    const float* Wlist[3] = {Wq, Wk, Wv};
    const float* blist[3] = {bq, bk, bv};

    for (int j = 0; j < 3; ++j) {
        __syncthreads();
        {
            const float4* g4 = reinterpret_cast<const float4*>(Wlist[j]);
            for (int i = tid; i < CC * (CC / 4); i += NTHREADS) {
                int r = i >> 5;
                int c = i & 31;
                reinterpret_cast<float4*>(Ws + r * LDA)[c] = g4[(size_t)r * 32 + c];
            }
        }
        __syncthreads();

        {
            const int tr  = warp >> 1;
            const int tc0 = (warp & 1) * 4;

            wmma::fragment<wmma::accumulator, 16, 16, 8, float> acc[4];
            #pragma unroll
            for (int f = 0; f < 4; ++f) wmma::fill_fragment(acc[f], 0.0f);

            for (int k0 = 0; k0 < CC; k0 += 8) {
                wmma::fragment<wmma::matrix_a, 16, 16, 8, wmma::precision::tf32, wmma::row_major> a;
                wmma::load_matrix_sync(a, Xs + tr * 16 * LDA + k0, LDA);
                #pragma unroll
                for (int i = 0; i < a.num_elements; ++i) a.x[i] = wmma::__float_to_tf32(a.x[i]);

                #pragma unroll
                for (int f = 0; f < 4; ++f) {
                    wmma::fragment<wmma::matrix_b, 16, 16, 8, wmma::precision::tf32, wmma::col_major> bf;
                    wmma::load_matrix_sync(bf, Ws + (tc0 + f) * 16 * LDA + k0, LDA);
                    #pragma unroll
                    for (int i = 0; i < bf.num_elements; ++i) bf.x[i] = wmma::__float_to_tf32(bf.x[i]);
                    wmma::mma_sync(acc[f], a, bf, acc[f]);
                }
            }
            #pragma unroll
            for (int f = 0; f < 4; ++f)
                wmma::store_matrix_sync(Outs + tr * 16 * LDA + (tc0 + f) * 16, acc[f], LDA,
                                        wmma::mem_row_major);
        }
        __syncthreads();

        {
            const float* bias = blist[j];
            const int bb = row0 / NN;
            const int n0 = row0 % NN;
            for (int i = tid; i < BM * CC; i += NTHREADS) {
                int r = i >> 7;
                int c = i & 127;
                float v = Outs[r * LDA + c] + bias[c];
                v = 0.5f * v * (1.0f + erff(v * 0.70710678118654752f));
                if (j < 2) {
                    int pc = 32 * (c & 3) + (c >> 2);       // permuted column
                    float* dst = (j == 0) ? g_q : g_k;
                    dst[(size_t)(row0 + r) * CC + pc] = f2tf32(v);
                } else {
                    // V^T bf16, permuted within 64-key tile
                    int nk    = n0 + r;
                    int tile  = nk & ~63;
                    int ntile = nk & 63;
                    int w     = ntile >> 1;
                    int half  = ntile & 1;
                    int pd    = 8 * (w & 3) + (w >> 2);     // dense word position
                    g_vt[((size_t)bb * CC + c) * NN + tile + 2 * pd + half] = __float2bfloat16(v);
                }
            }
        }
    }
}

// ---------------------------------------------------------------------------
// Kernel 2: flash attention. S in tf32 (accumulators stay in registers through
// softmax); PV in bf16. All operand smem accesses are LDS.128/STS.128 via the
// permuted layouts. m/l per-thread registers; cross-warp exchange via pmax[64][2].
// Pipeline (single-buffered K/V, FIFO-traced):
//   prologue: commit {K0,Q}; commit {V0}
//   iter t: wait<1> (K_t [+Q]) ; sync
//           S (regs) ; write pmax ; syncA
//           [commit K_{t+1}]
//           softmax in regs -> P (STS.128)
//           wait<has_next?1:0> (V_t) ; syncB
//           PV (O regs) ; syncC
//           [commit V_{t+1}]
// ---------------------------------------------------------------------------
__global__ __launch_bounds__(NTHREADS, 2)
void attn_kernel(float* __restrict__ out)
{
    extern __shared__ char smraw[];
    float*    Qs   = (float*)(smraw);                  // 64 x 144 f32 = 36864 B
    float*    Ks   = (float*)(smraw + 36864);          // 64 x 144 f32 = 36864 B
    uint32_t* Vt   = (uint32_t*)(smraw + 73728);       // 128 x 48 b32 = 24576 B
    uint32_t* Ps   = (uint32_t*)(smraw + 98304);       // 64 x 48 b32  = 12288 B
    float*    pmax = (float*)(smraw + 110592);         // [64][2]       =   512 B
    // total 111104 B -> 2 CTAs/SM

    const int tid  = threadIdx.x;
    const int warp = tid >> 5;
    const int lane = tid & 31;
    const int g    = lane >> 2;
    const int t    = lane & 3;
    const int tr   = warp >> 1;
    const int tch  = warp & 1;

    const int b     = blockIdx.y;
    const int qrow0 = blockIdx.x * BM;
    const int T     = NN / BN;

    const float*         qg   = g_q  + ((size_t)b * NN + qrow0) * CC;
    const float*         kgb  = g_k  + (size_t)b * NN * CC;
    const __nv_bfloat16* vtgb = g_vt + (size_t)b * CC * NN;

    // Prologue: G0 = {K0, Q}, G1 = {V0}
    issue_qk_load(Ks, kgb, tid);
    issue_qk_load(Qs, qg, tid);
    cp_commit();
    issue_vt_load(Vt, vtgb, tid);
    cp_commit();

    const int r0 = 16 * tr + g;
    const int r1 = r0 + 8;

    float m0 = -INFINITY, m1 = -INFINITY;
    float l0 = 0.0f, l1 = 0.0f;
    float o[8][4] = {};

    for (int kt = 0; kt < T; ++kt) {
        const bool has_next = (kt + 1 < T);

        cp_wait<1>();        // K_kt (and Q at kt=0) landed
        __syncthreads();

        // ---- S = Q K^T (tf32), accumulators in registers ----
        float sacc[4][4] = {};
        {
            const float* Qr0 = Qs + r0 * LDQW + 36 * t;
            const float* Qr1 = Qs + r1 * LDQW + 36 * t;
            #pragma unroll
            for (int v = 0; v < 8; ++v) {
                float4 q0 = *reinterpret_cast<const float4*>(Qr0 + 4 * v);
                float4 q1 = *reinterpret_cast<const float4*>(Qr1 + 4 * v);
                #pragma unroll
                for (int j = 0; j < 4; ++j) {
                    const float* Kr = Ks + (32 * tch + 8 * j + g) * LDQW + 36 * t;
                    float4 kf = *reinterpret_cast<const float4*>(Kr + 4 * v);
                    mma_tf32(sacc[j][0], sacc[j][1], sacc[j][2], sacc[j][3],
                             __float_as_uint(q0.x), __float_as_uint(q1.x),
                             __float_as_uint(q0.y), __float_as_uint(q1.y),
                             __float_as_uint(kf.x), __float_as_uint(kf.y));
                    mma_tf32(sacc[j][0], sacc[j][1], sacc[j][2], sacc[j][3],
                             __float_as_uint(q0.z), __float_as_uint(q1.z),
                             __float_as_uint(q0.w), __float_as_uint(q1.w),
                             __float_as_uint(kf.z), __float_as_uint(kf.w));
                }
            }
        }

        // ---- warp-half row max, exchange across warps via pmax ----
        {
            float mx0 = -INFINITY, mx1 = -INFINITY;
            #pragma unroll
            for (int j = 0; j < 4; ++j) {
                mx0 = fmaxf(mx0, fmaxf(sacc[j][0], sacc[j][1]));
                mx1 = fmaxf(mx1, fmaxf(sacc[j][2], sacc[j][3]));
            }
            mx0 = fmaxf(mx0, __shfl_xor_sync(0xffffffffu, mx0, 1));
            mx0 = fmaxf(mx0, __shfl_xor_sync(0xffffffffu, mx0, 2));
            mx1 = fmaxf(mx1, __shfl_xor_sync(0xffffffffu, mx1, 1));
            mx1 = fmaxf(mx1, __shfl_xor_sync(0xffffffffu, mx1, 2));
            if (t == 0) {
                pmax[2 * r0 + tch] = mx0;
                pmax[2 * r1 + tch] = mx1;
            }
        }
        __syncthreads();   // sync A

        if (has_next) {
            issue_qk_load(Ks, kgb + (size_t)(kt + 1) * BN * CC, tid);
            cp_commit();
        }

        // ---- softmax in registers; P -> bf16 STS.128 ----
        {
            float mh0 = fmaxf(pmax[2 * r0], pmax[2 * r0 + 1]);
            float mh1 = fmaxf(pmax[2 * r1], pmax[2 * r1 + 1]);
            float mn0 = fmaxf(m0, mh0);
            float mn1 = fmaxf(m1, mh1);
            float al0 = __expf(m0 - mn0);
            float al1 = __expf(m1 - mn1);
            m0 = mn0; m1 = mn1;

            uint32_t w0[4], w1[4];
            float ls0 = 0.0f, ls1 = 0.0f;
            #pragma unroll
            for (int j = 0; j < 4; ++j) {
                __nv_bfloat16 p00 = __float2bfloat16(__expf(sacc[j][0] - mn0));
                __nv_bfloat16 p01 = __float2bfloat16(__expf(sacc[j][1] - mn0));
                __nv_bfloat16 p10 = __float2bfloat16(__expf(sacc[j][2] - mn1));
                __nv_bfloat16 p11 = __float2bfloat16(__expf(sacc[j][3] - mn1));
                ls0 += __bfloat162float(p00) + __bfloat162float(p01);
                ls1 += __bfloat162float(p10) + __bfloat162float(p11);
                w0[j] = (uint32_t)__bfloat16_as_ushort(p00)
                      | ((uint32_t)__bfloat16_as_ushort(p01) << 16);
                w1[j] = (uint32_t)__bfloat16_as_ushort(p10)
                      | ((uint32_t)__bfloat16_as_ushort(p11) << 16);
            }
            ls0 += __shfl_xor_sync(0xffffffffu, ls0, 1);
            ls0 += __shfl_xor_sync(0xffffffffu, ls0, 2);
            ls1 += __shfl_xor_sync(0xffffffffu, ls1, 1);
            ls1 += __shfl_xor_sync(0xffffffffu, ls1, 2);
            l0 = l0 * al0 + ls0;
            l1 = l1 * al1 + ls1;

            *reinterpret_cast<uint4*>(Ps + r0 * LDPW + 12 * t + 4 * tch) =
                make_uint4(w0[0], w0[1], w0[2], w0[3]);
            *reinterpret_cast<uint4*>(Ps + r1 * LDPW + 12 * t + 4 * tch) =
                make_uint4(w1[0], w1[1], w1[2], w1[3]);

            // ---- O rescale by alpha (registers) ----
            #pragma unroll
            for (int f = 0; f < 8; ++f) {
                o[f][0] *= al0; o[f][1] *= al0;
                o[f][2] *= al1; o[f][3] *= al1;
            }
        }

        if (has_next) cp_wait<1>(); else cp_wait<0>();   // V_kt landed
        __syncthreads();   // sync B

        // ---- O += P V (bf16 m16n8k16) ----
        {
            uint4 pa = *reinterpret_cast<const uint4*>(Ps + r0 * LDPW + 12 * t);
            uint4 pb = *reinterpret_cast<const uint4*>(Ps + r0 * LDPW + 12 * t + 4);
            uint4 pc = *reinterpret_cast<const uint4*>(Ps + r1 * LDPW + 12 * t);
            uint4 pd = *reinterpret_cast<const uint4*>(Ps + r1 * LDPW + 12 * t + 4);
            uint32_t pw0[8] = {pa.x, pa.y, pa.z, pa.w, pb.x, pb.y, pb.z, pb.w};
            uint32_t pw1[8] = {pc.x, pc.y, pc.z, pc.w, pd.x, pd.y, pd.z, pd.w};

            #pragma unroll
            for (int f = 0; f < 8; ++f) {
                const uint32_t* vr = Vt + (64 * tch + 8 * f + g) * LDVW + 12 * t;
                uint4 va = *reinterpret_cast<const uint4*>(vr);
                uint4 vb = *reinterpret_cast<const uint4*>(vr + 4);
                uint32_t vw[8] = {va.x, va.y, va.z, va.w, vb.x, vb.y, vb.z, vb.w};
                #pragma unroll
                for (int kidx = 0; kidx < 4; ++kidx) {
                    mma_bf16(o[f][0], o[f][1], o[f][2], o[f][3],
                             pw0[2 * kidx], pw1[2 * kidx],
                             pw0[2 * kidx + 1], pw1[2 * kidx + 1],
                             vw[2 * kidx], vw[2 * kidx + 1]);
                }
            }
        }
        __syncthreads();   // sync C (guard Ps rewrite + Vt refill issue)

        if (has_next) {
            issue_vt_load(Vt, vtgb + (size_t)(kt + 1) * BN, tid);
            cp_commit();
        }
    }

    // ---- epilogue: reduce l across warp halves (reuse pmax), out = O / l ----
    if (t == 0) {
        pmax[2 * r0 + tch] = l0;
        pmax[2 * r1 + tch] = l1;
    }
    __syncthreads();
    {
        float inv0 = 1.0f / (pmax[2 * r0] + pmax[2 * r0 + 1]);
        float inv1 = 1.0f / (pmax[2 * r1] + pmax[2 * r1 + 1]);
        float* og = out + ((size_t)b * NN + qrow0) * CC;
        #pragma unroll
        for (int f = 0; f < 8; ++f) {
            int col = 64 * tch + 8 * f + 2 * t;
            *reinterpret_cast<float2*>(og + (size_t)r0 * CC + col) =
                make_float2(o[f][0] * inv0, o[f][1] * inv0);
            *reinterpret_cast<float2*>(og + (size_t)r1 * CC + col) =
                make_float2(o[f][2] * inv1, o[f][3] * inv1);
        }
    }
}

// ---------------------------------------------------------------------------
extern "C" void kernel_launch(void* const* d_in, const int* in_sizes, int n_in,
                              void* d_out, int out_size)
{
    const float* x  = (const float*)d_in[0];
    const float* Wq = (const float*)d_in[1];
    const float* bq = (const float*)d_in[2];
    const float* Wk = (const float*)d_in[3];
    const float* bk = (const float*)d_in[4];
    const float* Wv = (const float*)d_in[5];
    const float* bv = (const float*)d_in[6];
    float* out = (float*)d_out;

    const int smem_qkv  = (BM * LDA + CC * LDA + BM * LDA) * sizeof(float);   // ~136 KB
    const int smem_attn = 111104;                                             // ~108.5 KB -> 2 CTAs/SM

    cudaFuncSetAttribute(qkv_kernel,  cudaFuncAttributeMaxDynamicSharedMemorySize, smem_qkv);
    cudaFuncSetAttribute(attn_kernel, cudaFuncAttributeMaxDynamicSharedMemorySize, smem_attn);

    qkv_kernel<<<(BB * NN) / BM, NTHREADS, smem_qkv>>>(x, Wq, bq, Wk, bk, Wv, bv);

    dim3 grid(NN / BM, BB);
    attn_kernel<<<grid, NTHREADS, smem_attn>>>(out);
}

// round 14
// speedup vs baseline: 1.8354x; 1.2024x over previous
#include <cuda_runtime.h>
#include <cuda_bf16.h>
#include <cuda_fp16.h>
#include <mma.h>
#include <cmath>
#include <cstdint>

using namespace nvcuda;

// Problem dims
#define BB 4
#define NN 4096
#define CC 128

// Tiling
#define BM 64
#define BN 64
#define NTHREADS 256

// qkv kernel smem ld
#define LDA 136
// attention smem strides (b32 words):
//  Q/K rows (fp16): 4 groups of (16 data + 4 pad) words -> 80-word rows
//  V^T/P rows (bf16): 4 groups of (8 data + 4 pad) words -> 48-word rows
#define LDQW 80
#define LDVW 48
#define LDPW 48

// Scratch: Q,K fp16 word-permuted; V bf16 transposed [b][d][n], tile-permuted.
__device__ __half g_q[BB * NN * CC];
__device__ __half g_k[BB * NN * CC];
__device__ __nv_bfloat16 g_vt[BB * CC * NN];

// ---- helpers ---------------------------------------------------------------
__device__ __forceinline__ uint32_t smem_u32(const void* p) {
    return (uint32_t)__cvta_generic_to_shared(p);
}
__device__ __forceinline__ void cp_async16(uint32_t dst, const void* src) {
    asm volatile("cp.async.cg.shared.global [%0], [%1], 16;\n" :: "r"(dst), "l"(src));
}
__device__ __forceinline__ void cp_commit() {
    asm volatile("cp.async.commit_group;\n" ::: "memory");
}
template <int N>
__device__ __forceinline__ void cp_wait() {
    asm volatile("cp.async.wait_group %0;\n" :: "n"(N) : "memory");
}
// D += A*B, m16n8k16 fp16 (fp32 accum)
__device__ __forceinline__ void mma_f16(float& d0, float& d1, float& d2, float& d3,
                                        uint32_t a0, uint32_t a1, uint32_t a2, uint32_t a3,
                                        uint32_t b0, uint32_t b1) {
    asm volatile("mma.sync.aligned.m16n8k16.row.col.f32.f16.f16.f32 "
                 "{%0,%1,%2,%3}, {%4,%5,%6,%7}, {%8,%9}, {%0,%1,%2,%3};\n"
                 : "+f"(d0), "+f"(d1), "+f"(d2), "+f"(d3)
                 : "r"(a0), "r"(a1), "r"(a2), "r"(a3), "r"(b0), "r"(b1));
}
// D += A*B, m16n8k16 bf16 (fp32 accum)
__device__ __forceinline__ void mma_bf16(float& d0, float& d1, float& d2, float& d3,
                                         uint32_t a0, uint32_t a1, uint32_t a2, uint32_t a3,
                                         uint32_t b0, uint32_t b1) {
    asm volatile("mma.sync.aligned.m16n8k16.row.col.f32.bf16.bf16.f32 "
                 "{%0,%1,%2,%3}, {%4,%5,%6,%7}, {%8,%9}, {%0,%1,%2,%3};\n"
                 : "+f"(d0), "+f"(d1), "+f"(d2), "+f"(d3)
                 : "r"(a0), "r"(a1), "r"(a2), "r"(a3), "r"(b0), "r"(b1));
}

// Q/K fp16 tile: 64 rows x 16 chunks(16B = 8 halfs = 4 words).
// gmem rows permuted-dense (128 halfs); smem rows 80 words:
// chunk c -> group c>>2 (stride 20 words), within 4*(c&3).
__device__ __forceinline__ void issue_qk_load(uint32_t* dst, const __half* gsrc, int tid) {
    #pragma unroll
    for (int i = tid; i < BM * 16; i += NTHREADS) {
        int r = i >> 4;
        int c = i & 15;
        int smw = 20 * (c >> 2) + 4 * (c & 3);
        cp_async16(smem_u32(dst + r * LDQW + smw), gsrc + (size_t)r * CC + 8 * c);
    }
}
// V^T tile: 128 rows x 8 chunks(16B). smem rows 48 words: chunk c -> 12*(c>>1)+4*(c&1).
__device__ __forceinline__ void issue_vt_load(uint32_t* dst, const __nv_bfloat16* gsrc, int tid) {
    #pragma unroll
    for (int i = tid; i < 128 * 8; i += NTHREADS) {
        int d = i >> 3;
        int c = i & 7;
        int smw = 12 * (c >> 1) + 4 * (c & 1);
        cp_async16(smem_u32(dst + d * LDVW + smw), gsrc + (size_t)d * NN + 8 * c);
    }
}

// ---------------------------------------------------------------------------
// Kernel 1: fused QKV projection + bias + exact GELU.
// Q/K stored fp16 word-permuted: col c -> word w=c>>1 (half-slot h=c&1),
// dense word pos pd = 16*(w&3) + (w>>2), element 2*pd+h.
// V stored bf16 transposed, permuted within 64-key tiles.
// ---------------------------------------------------------------------------
__global__ __launch_bounds__(NTHREADS)
void qkv_kernel(const float* __restrict__ x,
                const float* __restrict__ Wq, const float* __restrict__ bq,
                const float* __restrict__ Wk, const float* __restrict__ bk,
                const float* __restrict__ Wv, const float* __restrict__ bv)
{
    extern __shared__ float sm[];
    float* Xs   = sm;
    float* Ws   = Xs + BM * LDA;
    float* Outs = Ws + CC * LDA;

    const int tid  = threadIdx.x;
    const int warp = tid >> 5;
    const int row0 = blockIdx.x * BM;

    {
        const float4* g4 = reinterpret_cast<const float4*>(x + (size_t)row0 * CC);
        for (int i = tid; i < BM * (CC / 4); i += NTHREADS) {
            int r = i >> 5;
            int c = i & 31;
            reinterpret_cast<float4*>(Xs + r * LDA)[c] = g4[(size_t)r * 32 + c];
        }
    }

    const float* Wlist[3] = {Wq, Wk, Wv};
    const float* blist[3] = {bq, bk, bv};

    for (int j = 0; j < 3; ++j) {
        __syncthreads();
        {
            const float4* g4 = reinterpret_cast<const float4*>(Wlist[j]);
            for (int i = tid; i < CC * (CC / 4); i += NTHREADS) {
                int r = i >> 5;
                int c = i & 31;
                reinterpret_cast<float4*>(Ws + r * LDA)[c] = g4[(size_t)r * 32 + c];
            }
        }
        __syncthreads();

        {
            const int tr  = warp >> 1;
            const int tc0 = (warp & 1) * 4;

            wmma::fragment<wmma::accumulator, 16, 16, 8, float> acc[4];
            #pragma unroll
            for (int f = 0; f < 4; ++f) wmma::fill_fragment(acc[f], 0.0f);

            for (int k0 = 0; k0 < CC; k0 += 8) {
                wmma::fragment<wmma::matrix_a, 16, 16, 8, wmma::precision::tf32, wmma::row_major> a;
                wmma::load_matrix_sync(a, Xs + tr * 16 * LDA + k0, LDA);
                #pragma unroll
                for (int i = 0; i < a.num_elements; ++i) a.x[i] = wmma::__float_to_tf32(a.x[i]);

                #pragma unroll
                for (int f = 0; f < 4; ++f) {
                    wmma::fragment<wmma::matrix_b, 16, 16, 8, wmma::precision::tf32, wmma::col_major> bf;
                    wmma::load_matrix_sync(bf, Ws + (tc0 + f) * 16 * LDA + k0, LDA);
                    #pragma unroll
                    for (int i = 0; i < bf.num_elements; ++i) bf.x[i] = wmma::__float_to_tf32(bf.x[i]);
                    wmma::mma_sync(acc[f], a, bf, acc[f]);
                }
            }
            #pragma unroll
            for (int f = 0; f < 4; ++f)
                wmma::store_matrix_sync(Outs + tr * 16 * LDA + (tc0 + f) * 16, acc[f], LDA,
                                        wmma::mem_row_major);
        }
        __syncthreads();

        {
            const float* bias = blist[j];
            const int bb = row0 / NN;
            const int n0 = row0 % NN;
            for (int i = tid; i < BM * CC; i += NTHREADS) {
                int r = i >> 7;
                int c = i & 127;
                float v = Outs[r * LDA + c] + bias[c];
                v = 0.5f * v * (1.0f + erff(v * 0.70710678118654752f));
                if (j < 2) {
                    int w  = c >> 1, h = c & 1;
                    int pd = 16 * (w & 3) + (w >> 2);
                    __half* dst = (j == 0) ? g_q : g_k;
                    dst[(size_t)(row0 + r) * CC + 2 * pd + h] = __float2half_rn(v);
                } else {
                    int nk    = n0 + r;
                    int tile  = nk & ~63;
                    int ntile = nk & 63;
                    int w     = ntile >> 1;
                    int hv    = ntile & 1;
                    int pd    = 8 * (w & 3) + (w >> 2);
                    g_vt[((size_t)bb * CC + c) * NN + tile + 2 * pd + hv] = __float2bfloat16(v);
                }
            }
        }
    }
}

// ---------------------------------------------------------------------------
// Kernel 2: flash attention. S = QK^T in fp16 (fp32 accum, registers through
// softmax); PV in bf16. All smem operand accesses LDS.128/STS.128.
// Pipeline (single-buffered K/V, FIFO-traced):
//   prologue: commit {K0,Q}; commit {V0}
//   iter t: wait<1> (K_t [+Q]) ; sync
//           S (regs) ; pmax exchange ; syncA
//           [commit K_{t+1}]
//           softmax regs -> P STS.128
//           wait<has_next?1:0> (V_t) ; syncB
//           PV (O regs) ; syncC
//           [commit V_{t+1}]
// ---------------------------------------------------------------------------
__global__ __launch_bounds__(NTHREADS, 2)
void attn_kernel(float* __restrict__ out)
{
    extern __shared__ char smraw[];
    uint32_t* Qs   = (uint32_t*)(smraw);               // 64 x 80 b32 = 20480 B
    uint32_t* Ks   = (uint32_t*)(smraw + 20480);       // 64 x 80 b32 = 20480 B
    uint32_t* Vt   = (uint32_t*)(smraw + 40960);       // 128 x 48 b32 = 24576 B
    uint32_t* Ps   = (uint32_t*)(smraw + 65536);       // 64 x 48 b32  = 12288 B
    float*    pmax = (float*)(smraw + 77824);          // [64][2]      =   512 B
    // total 78336 B -> 2 CTAs/SM

    const int tid  = threadIdx.x;
    const int warp = tid >> 5;
    const int lane = tid & 31;
    const int g    = lane >> 2;
    const int t    = lane & 3;
    const int tr   = warp >> 1;
    const int tch  = warp & 1;

    const int b     = blockIdx.y;
    const int qrow0 = blockIdx.x * BM;
    const int T     = NN / BN;

    const __half*        qg   = g_q  + ((size_t)b * NN + qrow0) * CC;
    const __half*        kgb  = g_k  + (size_t)b * NN * CC;
    const __nv_bfloat16* vtgb = g_vt + (size_t)b * CC * NN;

    // Prologue: G0 = {K0, Q}, G1 = {V0}
    issue_qk_load(Ks, kgb, tid);
    issue_qk_load(Qs, qg, tid);
    cp_commit();
    issue_vt_load(Vt, vtgb, tid);
    cp_commit();

    const int r0 = 16 * tr + g;
    const int r1 = r0 + 8;

    float m0 = -INFINITY, m1 = -INFINITY;
    float l0 = 0.0f, l1 = 0.0f;
    float o[8][4] = {};

    for (int kt = 0; kt < T; ++kt) {
        const bool has_next = (kt + 1 < T);

        cp_wait<1>();        // K_kt (and Q at kt=0) landed
        __syncthreads();

        // ---- S = Q K^T (fp16 m16n8k16), accumulators in registers ----
        float sacc[4][4] = {};
        {
            const uint32_t* Qr0 = Qs + r0 * LDQW + 20 * t;
            const uint32_t* Qr1 = Qs + r1 * LDQW + 20 * t;
            #pragma unroll
            for (int v = 0; v < 4; ++v) {
                uint4 q0 = *reinterpret_cast<const uint4*>(Qr0 + 4 * v);
                uint4 q1 = *reinterpret_cast<const uint4*>(Qr1 + 4 * v);
                #pragma unroll
                for (int j = 0; j < 4; ++j) {
                    const uint32_t* Kr = Ks + (32 * tch + 8 * j + g) * LDQW + 20 * t;
                    uint4 kf = *reinterpret_cast<const uint4*>(Kr + 4 * v);
                    mma_f16(sacc[j][0], sacc[j][1], sacc[j][2], sacc[j][3],
                            q0.x, q1.x, q0.y, q1.y, kf.x, kf.y);
                    mma_f16(sacc[j][0], sacc[j][1], sacc[j][2], sacc[j][3],
                            q0.z, q1.z, q0.w, q1.w, kf.z, kf.w);
                }
            }
        }

        // ---- warp-half row max, exchange across warps via pmax ----
        {
            float mx0 = -INFINITY, mx1 = -INFINITY;
            #pragma unroll
            for (int j = 0; j < 4; ++j) {
                mx0 = fmaxf(mx0, fmaxf(sacc[j][0], sacc[j][1]));
                mx1 = fmaxf(mx1, fmaxf(sacc[j][2], sacc[j][3]));
            }
            mx0 = fmaxf(mx0, __shfl_xor_sync(0xffffffffu, mx0, 1));
            mx0 = fmaxf(mx0, __shfl_xor_sync(0xffffffffu, mx0, 2));
            mx1 = fmaxf(mx1, __shfl_xor_sync(0xffffffffu, mx1, 1));
            mx1 = fmaxf(mx1, __shfl_xor_sync(0xffffffffu, mx1, 2));
            if (t == 0) {
                pmax[2 * r0 + tch] = mx0;
                pmax[2 * r1 + tch] = mx1;
            }
        }
        __syncthreads();   // sync A

        if (has_next) {
            issue_qk_load(Ks, kgb + (size_t)(kt + 1) * BN * CC, tid);
            cp_commit();
        }

        // ---- softmax in registers; P -> bf16 STS.128 ----
        {
            float mh0 = fmaxf(pmax[2 * r0], pmax[2 * r0 + 1]);
            float mh1 = fmaxf(pmax[2 * r1], pmax[2 * r1 + 1]);
            float mn0 = fmaxf(m0, mh0);
            float mn1 = fmaxf(m1, mh1);
            float al0 = __expf(m0 - mn0);
            float al1 = __expf(m1 - mn1);
            m0 = mn0; m1 = mn1;

            uint32_t w0[4], w1[4];
            float ls0 = 0.0f, ls1 = 0.0f;
            #pragma unroll
            for (int j = 0; j < 4; ++j) {
                __nv_bfloat16 p00 = __float2bfloat16(__expf(sacc[j][0] - mn0));
                __nv_bfloat16 p01 = __float2bfloat16(__expf(sacc[j][1] - mn0));
                __nv_bfloat16 p10 = __float2bfloat16(__expf(sacc[j][2] - mn1));
                __nv_bfloat16 p11 = __float2bfloat16(__expf(sacc[j][3] - mn1));
                ls0 += __bfloat162float(p00) + __bfloat162float(p01);
                ls1 += __bfloat162float(p10) + __bfloat162float(p11);
                w0[j] = (uint32_t)__bfloat16_as_ushort(p00)
                      | ((uint32_t)__bfloat16_as_ushort(p01) << 16);
                w1[j] = (uint32_t)__bfloat16_as_ushort(p10)
                      | ((uint32_t)__bfloat16_as_ushort(p11) << 16);
            }
            ls0 += __shfl_xor_sync(0xffffffffu, ls0, 1);
            ls0 += __shfl_xor_sync(0xffffffffu, ls0, 2);
            ls1 += __shfl_xor_sync(0xffffffffu, ls1, 1);
            ls1 += __shfl_xor_sync(0xffffffffu, ls1, 2);
            l0 = l0 * al0 + ls0;
            l1 = l1 * al1 + ls1;

            *reinterpret_cast<uint4*>(Ps + r0 * LDPW + 12 * t + 4 * tch) =
                make_uint4(w0[0], w0[1], w0[2], w0[3]);
            *reinterpret_cast<uint4*>(Ps + r1 * LDPW + 12 * t + 4 * tch) =
                make_uint4(w1[0], w1[1], w1[2], w1[3]);

            #pragma unroll
            for (int f = 0; f < 8; ++f) {
                o[f][0] *= al0; o[f][1] *= al0;
                o[f][2] *= al1; o[f][3] *= al1;
            }
        }

        if (has_next) cp_wait<1>(); else cp_wait<0>();   // V_kt landed
        __syncthreads();   // sync B

        // ---- O += P V (bf16 m16n8k16) ----
        {
            uint4 pa = *reinterpret_cast<const uint4*>(Ps + r0 * LDPW + 12 * t);
            uint4 pb = *reinterpret_cast<const uint4*>(Ps + r0 * LDPW + 12 * t + 4);
            uint4 pc = *reinterpret_cast<const uint4*>(Ps + r1 * LDPW + 12 * t);
            uint4 pd = *reinterpret_cast<const uint4*>(Ps + r1 * LDPW + 12 * t + 4);
            uint32_t pw0[8] = {pa.x, pa.y, pa.z, pa.w, pb.x, pb.y, pb.z, pb.w};
            uint32_t pw1[8] = {pc.x, pc.y, pc.z, pc.w, pd.x, pd.y, pd.z, pd.w};

            #pragma unroll
            for (int f = 0; f < 8; ++f) {
                const uint32_t* vr = Vt + (64 * tch + 8 * f + g) * LDVW + 12 * t;
                uint4 va = *reinterpret_cast<const uint4*>(vr);
                uint4 vb = *reinterpret_cast<const uint4*>(vr + 4);
                uint32_t vw[8] = {va.x, va.y, va.z, va.w, vb.x, vb.y, vb.z, vb.w};
                #pragma unroll
                for (int kidx = 0; kidx < 4; ++kidx) {
                    mma_bf16(o[f][0], o[f][1], o[f][2], o[f][3],
                             pw0[2 * kidx], pw1[2 * kidx],
                             pw0[2 * kidx + 1], pw1[2 * kidx + 1],
                             vw[2 * kidx], vw[2 * kidx + 1]);
                }
            }
        }
        __syncthreads();   // sync C

        if (has_next) {
            issue_vt_load(Vt, vtgb + (size_t)(kt + 1) * BN, tid);
            cp_commit();
        }
    }

    // ---- epilogue: reduce l across warp halves (reuse pmax), out = O / l ----
    if (t == 0) {
        pmax[2 * r0 + tch] = l0;
        pmax[2 * r1 + tch] = l1;
    }
    __syncthreads();
    {
        float inv0 = 1.0f / (pmax[2 * r0] + pmax[2 * r0 + 1]);
        float inv1 = 1.0f / (pmax[2 * r1] + pmax[2 * r1 + 1]);
        float* og = out + ((size_t)b * NN + qrow0) * CC;
        #pragma unroll
        for (int f = 0; f < 8; ++f) {
            int col = 64 * tch + 8 * f + 2 * t;
            *reinterpret_cast<float2*>(og + (size_t)r0 * CC + col) =
                make_float2(o[f][0] * inv0, o[f][1] * inv0);
            *reinterpret_cast<float2*>(og + (size_t)r1 * CC + col) =
                make_float2(o[f][2] * inv1, o[f][3] * inv1);
        }
    }
}

// ---------------------------------------------------------------------------
extern "C" void kernel_launch(void* const* d_in, const int* in_sizes, int n_in,
                              void* d_out, int out_size)
{
    const float* x  = (const float*)d_in[0];
    const float* Wq = (const float*)d_in[1];
    const float* bq = (const float*)d_in[2];
    const float* Wk = (const float*)d_in[3];
    const float* bk = (const float*)d_in[4];
    const float* Wv = (const float*)d_in[5];
    const float* bv = (const float*)d_in[6];
    float* out = (float*)d_out;

    const int smem_qkv  = (BM * LDA + CC * LDA + BM * LDA) * sizeof(float);   // ~136 KB
    const int smem_attn = 78336;                                              // ~76.5 KB -> 2 CTAs/SM

    cudaFuncSetAttribute(qkv_kernel,  cudaFuncAttributeMaxDynamicSharedMemorySize, smem_qkv);
    cudaFuncSetAttribute(attn_kernel, cudaFuncAttributeMaxDynamicSharedMemorySize, smem_attn);

    qkv_kernel<<<(BB * NN) / BM, NTHREADS, smem_qkv>>>(x, Wq, bq, Wk, bk, Wv, bv);

    dim3 grid(NN / BM, BB);
    attn_kernel<<<grid, NTHREADS, smem_attn>>>(out);
}